// round 1
// baseline (speedup 1.0000x reference)
#include <cuda_runtime.h>
#include <math.h>
#include <stdint.h>

// ---------------- problem constants ----------------
#define QLEN   512
#define MEMLEN 512
#define KLEN   1024         // QLEN + MEMLEN
#define BSZ    8
#define NH     16
#define DH     64
#define DM     1024
#define DI     4096
#define NL     6
#define NTOK   32000
#define HD     1024         // NH*DH
#define ROWS   (QLEN*BSZ)   // 4096
#define KROWS  (KLEN*BSZ)   // 8192
#define SCALE  0.125f       // 1/sqrt(64)

// ---------------- scratch (device globals; no allocation allowed) ----------------
__device__ float g_core [ROWS  * DM];            // 16.8 MB
__device__ float g_xmem [KROWS * DM];            // 33.5 MB
__device__ float g_q    [ROWS  * DM];
__device__ float g_qrw  [ROWS  * DM];
__device__ float g_qrr  [ROWS  * DM];
__device__ float g_kv   [KROWS * 2 * HD];        // 67 MB  (k | v interleaved per row)
__device__ float g_pos  [KLEN  * DM];
__device__ float g_rk   [KLEN  * DM];
__device__ float g_sc   [(size_t)BSZ * NH * QLEN * KLEN];  // 268 MB : AC then prob
__device__ float g_bd   [(size_t)NH * ROWS * KLEN];        // 268 MB : BD raw (unshifted)
__device__ float g_vec  [ROWS * DM];
__device__ float g_tmp  [ROWS * DM];             // attn_out / ff_out
__device__ float g_ffh  [ROWS * DI];             // 67 MB
__device__ float g_logit[(size_t)ROWS * NTOK];   // 524 MB

// ---------------- SGEMM: C = A * B(^T) , 128x128 tile, 8x8/thread ----------------
// TB=0: B is KxN (NN).  TB=1: B is NxK (NT).
// 2-level batch: bz -> (b1 = bz/batch2, b2 = bz%batch2), per-operand strides.
// epi: 0 none, 1 +bias[n], 2 relu(+bias[n])
template <int TB>
__global__ void __launch_bounds__(256, 2)
sgemm(const float* __restrict__ A, const float* __restrict__ B, float* __restrict__ C,
      int M, int N, int K, int lda, int ldb, int ldc,
      long sA1, long sA2, long sB1, long sB2, long sC1, long sC2, int batch2,
      const float* __restrict__ bias, int epi)
{
    __shared__ float As[8][128];
    __shared__ float Bs[8][132];

    const int bz = blockIdx.z;
    const int b1 = bz / batch2, b2 = bz % batch2;
    A += (long)b1 * sA1 + (long)b2 * sA2;
    B += (long)b1 * sB1 + (long)b2 * sB2;
    C += (long)b1 * sC1 + (long)b2 * sC2;

    const int m0 = blockIdx.y * 128;
    const int n0 = blockIdx.x * 128;
    const int tid = threadIdx.x;
    const int tx = tid & 15, ty = tid >> 4;

    float acc[8][8];
#pragma unroll
    for (int r = 0; r < 8; r++)
#pragma unroll
        for (int c = 0; c < 8; c++) acc[r][c] = 0.f;

    const int arow = tid >> 1;
    const int acol = (tid & 1) * 4;

    for (int k0 = 0; k0 < K; k0 += 8) {
        // load A tile (K is always a multiple of 8 in this model)
        {
            float a0 = 0.f, a1 = 0.f, a2 = 0.f, a3 = 0.f;
            const int gm = m0 + arow;
            if (gm < M) {
                const float* ap = A + (long)gm * lda + k0 + acol;
                a0 = ap[0]; a1 = ap[1]; a2 = ap[2]; a3 = ap[3];
            }
            As[acol + 0][arow] = a0;
            As[acol + 1][arow] = a1;
            As[acol + 2][arow] = a2;
            As[acol + 3][arow] = a3;
        }
        // load B tile
        if (TB == 0) {
            const int kk = tid >> 5, n4 = (tid & 31) * 4;
            const float* bp = B + (long)(k0 + kk) * ldb + n0 + n4;
#pragma unroll
            for (int i = 0; i < 4; i++)
                Bs[kk][n4 + i] = (n0 + n4 + i < N) ? bp[i] : 0.f;
        } else {
            const int n = tid & 127, kk0 = (tid >> 7) * 4;
            float bv[4] = {0.f, 0.f, 0.f, 0.f};
            if (n0 + n < N) {
                const float* bp = B + (long)(n0 + n) * ldb + k0 + kk0;
                bv[0] = bp[0]; bv[1] = bp[1]; bv[2] = bp[2]; bv[3] = bp[3];
            }
#pragma unroll
            for (int i = 0; i < 4; i++) Bs[kk0 + i][n] = bv[i];
        }
        __syncthreads();

#pragma unroll
        for (int kk = 0; kk < 8; kk++) {
            float av[8], bv[8];
#pragma unroll
            for (int r = 0; r < 8; r++) av[r] = As[kk][ty * 8 + r];
#pragma unroll
            for (int c = 0; c < 8; c++) bv[c] = Bs[kk][tx * 8 + c];
#pragma unroll
            for (int r = 0; r < 8; r++)
#pragma unroll
                for (int c = 0; c < 8; c++) acc[r][c] += av[r] * bv[c];
        }
        __syncthreads();
    }

#pragma unroll
    for (int r = 0; r < 8; r++) {
        const int gm = m0 + ty * 8 + r;
        if (gm >= M) continue;
#pragma unroll
        for (int c = 0; c < 8; c++) {
            const int gn = n0 + tx * 8 + c;
            if (gn >= N) continue;
            float v = acc[r][c];
            if (epi >= 1) v += bias[gn];
            if (epi == 2) v = fmaxf(v, 0.f);
            C[(long)gm * ldc + gn] = v;
        }
    }
}

// ---------------- element-wise / reduction kernels ----------------

__global__ void embed_kernel(const int* __restrict__ data, const float* __restrict__ embW,
                             float* __restrict__ core)
{
    long idx = (long)blockIdx.x * 256 + threadIdx.x;
    if (idx >= (long)ROWS * DM) return;
    int r = (int)(idx >> 10), d = (int)(idx & 1023);
    core[idx] = embW[(long)data[r] * DM + d];
}

__global__ void pos_kernel(float* __restrict__ pos)
{
    long idx = (long)blockIdx.x * 256 + threadIdx.x;
    if (idx >= (long)KLEN * DM) return;
    int j = (int)(idx >> 10), d = (int)(idx & 1023);
    float p = (float)(KLEN - 1 - j);
    int t = (d < 512) ? d : d - 512;
    float invf = expf(-((2.0f * (float)t) / (float)DM) * logf(10000.0f));
    float a = p * invf;
    pos[idx] = (d < 512) ? sinf(a) : cosf(a);
}

__global__ void qbias_kernel(const float* __restrict__ q,
                             const float* __restrict__ rwb, const float* __restrict__ rrb,
                             float* __restrict__ qrw, float* __restrict__ qrr)
{
    long idx = (long)blockIdx.x * 256 + threadIdx.x;
    if (idx >= (long)ROWS * DM) return;
    int hd = (int)(idx & 1023);
    float v = q[idx];
    qrw[idx] = v + rwb[hd];
    qrr[idx] = v + rrb[hd];
}

// scores[b,n,i,:] = softmax over j of mask( (AC + shifted BD) * SCALE )
// shifted BD[i,j] = bd_raw[n, i*BSZ+b, j + QLEN-1-i]  (valid for all unmasked j)
__global__ void attn_softmax_kernel(float* __restrict__ sc, const float* __restrict__ bd)
{
    const int i = blockIdx.x, n = blockIdx.y, b = blockIdx.z;
    const int t = threadIdx.x;
    float* row = sc + ((((long)b * NH + n) * QLEN + i) * KLEN);
    const float* bdr = bd + (((long)n * ROWS + (i * BSZ + b)) * KLEN);
    const int limit = i + MEMLEN;       // keep j <= limit
    const int shift = QLEN - 1 - i;

    __shared__ float red[256];
    float v[4];
    float m = -1e30f;
#pragma unroll
    for (int k = 0; k < 4; k++) {
        int j = t + k * 256;
        float x = -1e30f;
        if (j <= limit) x = (row[j] + bdr[j + shift]) * SCALE;
        v[k] = x;
        m = fmaxf(m, x);
    }
    red[t] = m; __syncthreads();
    for (int o = 128; o > 0; o >>= 1) { if (t < o) red[t] = fmaxf(red[t], red[t + o]); __syncthreads(); }
    const float M = red[0];
    __syncthreads();

    float s = 0.f;
#pragma unroll
    for (int k = 0; k < 4; k++) { float e = expf(v[k] - M); v[k] = e; s += e; }
    red[t] = s; __syncthreads();
    for (int o = 128; o > 0; o >>= 1) { if (t < o) red[t] += red[t + o]; __syncthreads(); }
    const float inv = 1.0f / red[0];
#pragma unroll
    for (int k = 0; k < 4; k++) row[t + k * 256] = v[k] * inv;
}

// out = LayerNorm(x + y) * g + b  (row = 1024 elems, one block/row)
__global__ void ln_kernel(const float* __restrict__ x, const float* __restrict__ y,
                          const float* __restrict__ g, const float* __restrict__ b,
                          float* __restrict__ out)
{
    const int r = blockIdx.x, t = threadIdx.x;
    __shared__ float red[256];
    const float* xr = x + (long)r * DM;
    const float* yr = y + (long)r * DM;
    float loc[4];
    float s = 0.f;
#pragma unroll
    for (int k = 0; k < 4; k++) { float v = xr[t + k * 256] + yr[t + k * 256]; loc[k] = v; s += v; }
    red[t] = s; __syncthreads();
    for (int o = 128; o > 0; o >>= 1) { if (t < o) red[t] += red[t + o]; __syncthreads(); }
    const float mu = red[0] * (1.0f / DM);
    __syncthreads();
    float s2 = 0.f;
#pragma unroll
    for (int k = 0; k < 4; k++) { float d = loc[k] - mu; s2 += d * d; }
    red[t] = s2; __syncthreads();
    for (int o = 128; o > 0; o >>= 1) { if (t < o) red[t] += red[t + o]; __syncthreads(); }
    const float rstd = rsqrtf(red[0] * (1.0f / DM) + 1e-5f);
#pragma unroll
    for (int k = 0; k < 4; k++) {
        int d = t + k * 256;
        out[(long)r * DM + d] = (loc[k] - mu) * rstd * g[d] + b[d];
    }
}

// loss[r] = logsumexp(logits[r,:]) - logits[r,target[r]]
__global__ void loss_kernel(const float* __restrict__ logits, const int* __restrict__ target,
                            float* __restrict__ out)
{
    const int r = blockIdx.x, t = threadIdx.x;
    __shared__ float red[256];
    const float* lr = logits + (long)r * NTOK;
    float m = -1e30f;
    for (int j = t; j < NTOK; j += 256) m = fmaxf(m, lr[j]);
    red[t] = m; __syncthreads();
    for (int o = 128; o > 0; o >>= 1) { if (t < o) red[t] = fmaxf(red[t], red[t + o]); __syncthreads(); }
    const float M = red[0];
    __syncthreads();
    float s = 0.f;
    for (int j = t; j < NTOK; j += 256) s += expf(lr[j] - M);
    red[t] = s; __syncthreads();
    for (int o = 128; o > 0; o >>= 1) { if (t < o) red[t] += red[t + o]; __syncthreads(); }
    if (t == 0) out[r] = (logf(red[0]) + M) - lr[target[r]];
}

// ---------------- host orchestration ----------------

static inline dim3 g2(int N, int M, int bz = 1) { return dim3((N + 127) / 128, (M + 127) / 128, bz); }

extern "C" void kernel_launch(void* const* d_in, const int* in_sizes, int n_in,
                              void* d_out, int out_size)
{
    const int*   data   = (const int*)  d_in[0];
    const int*   target = (const int*)  d_in[1];
    const float* memory = (const float*)d_in[2];
    const float* embW   = (const float*)d_in[3];
    const float* rwb    = (const float*)d_in[4];
    const float* rrb    = (const float*)d_in[5];
    const float* Wq     = (const float*)d_in[6];
    const float* Wkv    = (const float*)d_in[7];
    const float* Wr     = (const float*)d_in[8];
    const float* Wo     = (const float*)d_in[9];
    const float* W1     = (const float*)d_in[10];
    const float* b1     = (const float*)d_in[11];
    const float* W2     = (const float*)d_in[12];
    const float* b2     = (const float*)d_in[13];
    const float* ln1g   = (const float*)d_in[14];
    const float* ln1b   = (const float*)d_in[15];
    const float* ln2g   = (const float*)d_in[16];
    const float* ln2b   = (const float*)d_in[17];

    float* out      = (float*)d_out;
    float* out_loss = out;
    float* out_mems = out + ROWS;   // [6, 512, 8, 1024]

    float *core, *xmem, *qb, *qrw, *qrr, *kv, *pos, *rk, *sc, *bd, *vec, *tmp, *ffh, *logit;
    cudaGetSymbolAddress((void**)&core,  g_core);
    cudaGetSymbolAddress((void**)&xmem,  g_xmem);
    cudaGetSymbolAddress((void**)&qb,    g_q);
    cudaGetSymbolAddress((void**)&qrw,   g_qrw);
    cudaGetSymbolAddress((void**)&qrr,   g_qrr);
    cudaGetSymbolAddress((void**)&kv,    g_kv);
    cudaGetSymbolAddress((void**)&pos,   g_pos);
    cudaGetSymbolAddress((void**)&rk,    g_rk);
    cudaGetSymbolAddress((void**)&sc,    g_sc);
    cudaGetSymbolAddress((void**)&bd,    g_bd);
    cudaGetSymbolAddress((void**)&vec,   g_vec);
    cudaGetSymbolAddress((void**)&tmp,   g_tmp);
    cudaGetSymbolAddress((void**)&ffh,   g_ffh);
    cudaGetSymbolAddress((void**)&logit, g_logit);

    const size_t coreBytes = (size_t)ROWS * DM * sizeof(float);

    // embedding + positional encodings
    embed_kernel<<<(ROWS * DM + 255) / 256, 256>>>(data, embW, core);
    pos_kernel  <<<(KLEN * DM + 255) / 256, 256>>>(pos);

    // new_mems[0] = word_emb   (qlen == mem_len, so new_mems[l] == hids[l])
    cudaMemcpyAsync(out_mems, core, coreBytes, cudaMemcpyDeviceToDevice);

    for (int l = 0; l < NL; l++) {
        // x_mem = concat(mem[l], core)
        cudaMemcpyAsync(xmem,             memory + (size_t)l * ROWS * DM, coreBytes, cudaMemcpyDeviceToDevice);
        cudaMemcpyAsync(xmem + ROWS * DM, core,                           coreBytes, cudaMemcpyDeviceToDevice);

        // kv = x_mem @ Wkv[l]   [8192,1024]x[1024,2048]
        sgemm<0><<<g2(2 * HD, KROWS), 256>>>(xmem, Wkv + (size_t)l * DM * 2 * HD, kv,
                                             KROWS, 2 * HD, DM, DM, 2 * HD, 2 * HD,
                                             0, 0, 0, 0, 0, 0, 1, nullptr, 0);
        // q = core @ Wq[l]
        sgemm<0><<<g2(HD, ROWS), 256>>>(core, Wq + (size_t)l * DM * HD, qb,
                                        ROWS, HD, DM, DM, HD, HD,
                                        0, 0, 0, 0, 0, 0, 1, nullptr, 0);
        qbias_kernel<<<(ROWS * DM + 255) / 256, 256>>>(qb, rwb, rrb, qrw, qrr);

        // r_k = pos @ Wr[l]
        sgemm<0><<<g2(HD, KLEN), 256>>>(pos, Wr + (size_t)l * DM * HD, rk,
                                        KLEN, HD, DM, DM, HD, HD,
                                        0, 0, 0, 0, 0, 0, 1, nullptr, 0);

        // AC[b,n,i,j] = (q+rwb)[i,b,n,:] . k[j,b,n,:]   (NT, batched over b*n)
        sgemm<1><<<g2(KLEN, QLEN, BSZ * NH), 256>>>(qrw, kv, sc,
            QLEN, KLEN, DH, BSZ * DM, BSZ * 2 * HD, KLEN,
            /*A*/ (long)DM, (long)DH,
            /*B*/ (long)2 * HD, (long)DH,
            /*C*/ (long)NH * QLEN * KLEN, (long)QLEN * KLEN,
            NH, nullptr, 0);

        // BDraw[n,(i*8+b),j] = (q+rrb)[.,n,:] . r_k[j,n,:]   (NT, batched over n)
        sgemm<1><<<g2(KLEN, ROWS, NH), 256>>>(qrr, rk, bd,
            ROWS, KLEN, DH, DM, DM, KLEN,
            0, (long)DH,
            0, (long)DH,
            0, (long)ROWS * KLEN,
            NH, nullptr, 0);

        // masked softmax with rel-shift applied on the fly
        attn_softmax_kernel<<<dim3(QLEN, NH, BSZ), 256>>>(sc, bd);

        // vec[i,b,n,:] = prob[b,n,i,:] @ v[:,b,n,:]   (NN, batched over b*n)
        sgemm<0><<<g2(DH, QLEN, BSZ * NH), 256>>>(sc, kv + HD, vec,
            QLEN, DH, KLEN, KLEN, BSZ * 2 * HD, BSZ * DM,
            (long)NH * QLEN * KLEN, (long)QLEN * KLEN,
            (long)2 * HD, (long)DH,
            (long)DM, (long)DH,
            NH, nullptr, 0);

        // attn_out = vec @ Wo[l]
        sgemm<0><<<g2(DM, ROWS), 256>>>(vec, Wo + (size_t)l * HD * DM, tmp,
                                        ROWS, DM, HD, HD, DM, DM,
                                        0, 0, 0, 0, 0, 0, 1, nullptr, 0);
        // core = LN(core + attn_out)
        ln_kernel<<<ROWS, 256>>>(core, tmp, ln1g + (size_t)l * DM, ln1b + (size_t)l * DM, core);

        // ffh = relu(core @ W1 + b1)
        sgemm<0><<<g2(DI, ROWS), 256>>>(core, W1 + (size_t)l * DM * DI, ffh,
                                        ROWS, DI, DM, DM, DI, DI,
                                        0, 0, 0, 0, 0, 0, 1, b1 + (size_t)l * DI, 2);
        // ff_out = ffh @ W2 + b2
        sgemm<0><<<g2(DM, ROWS), 256>>>(ffh, W2 + (size_t)l * DI * DM, tmp,
                                        ROWS, DM, DI, DI, DM, DM,
                                        0, 0, 0, 0, 0, 0, 1, b2 + (size_t)l * DM, 1);
        // core = LN(core + ff_out)
        ln_kernel<<<ROWS, 256>>>(core, tmp, ln2g + (size_t)l * DM, ln2b + (size_t)l * DM, core);

        if (l < NL - 1)
            cudaMemcpyAsync(out_mems + (size_t)(l + 1) * ROWS * DM, core, coreBytes,
                            cudaMemcpyDeviceToDevice);
    }

    // logits = core @ emb_W^T   (NT)  [4096,1024]x[32000,1024]^T
    sgemm<1><<<g2(NTOK, ROWS), 256>>>(core, embW, logit,
                                      ROWS, NTOK, DM, DM, DM, NTOK,
                                      0, 0, 0, 0, 0, 0, 1, nullptr, 0);
    // loss
    loss_kernel<<<ROWS, 256>>>(logit, target, out_loss);

    (void)in_sizes; (void)n_in; (void)out_size;
}

// round 2
// speedup vs baseline: 1.1549x; 1.1549x over previous
#include <cuda_runtime.h>
#include <math.h>
#include <stdint.h>

// ---------------- problem constants ----------------
#define QLEN   512
#define MEMLEN 512
#define KLEN   1024         // QLEN + MEMLEN
#define BSZ    8
#define NH     16
#define DH     64
#define DM     1024
#define DI     4096
#define NL     6
#define NTOK   32000
#define HD     1024         // NH*DH
#define ROWS   (QLEN*BSZ)   // 4096
#define KROWS  (KLEN*BSZ)   // 8192
#define SCALE  0.125f       // 1/sqrt(64)

// ---------------- scratch (device globals; no allocation allowed) ----------------
__device__ float g_core [ROWS  * DM];
__device__ float g_xmem [KROWS * DM];
__device__ float g_q    [ROWS  * DM];
__device__ float g_qrw  [ROWS  * DM];
__device__ float g_qrr  [ROWS  * DM];
__device__ float g_kv   [KROWS * 2 * HD];
__device__ float g_pos  [KLEN  * DM];
__device__ float g_rk   [KLEN  * DM];
__device__ float g_sc   [(size_t)BSZ * NH * QLEN * KLEN];  // AC then prob
__device__ float g_bd   [(size_t)NH * ROWS * KLEN];        // BD raw (unshifted)
__device__ float g_vec  [ROWS * DM];
__device__ float g_tmp  [ROWS * DM];
__device__ float g_ffh  [ROWS * DI];
__device__ float g_logit[(size_t)ROWS * NTOK];

// ---------------- tf32 helpers ----------------
__device__ __forceinline__ uint32_t f2tf32(float x) {
    uint32_t r;
    asm("cvt.rna.tf32.f32 %0, %1;" : "=r"(r) : "f"(x));
    return r;
}

__device__ __forceinline__ void mma_tf32(float* d, const uint32_t* a, const uint32_t* b) {
    asm volatile(
        "mma.sync.aligned.m16n8k8.row.col.f32.tf32.tf32.f32 "
        "{%0,%1,%2,%3}, {%4,%5,%6,%7}, {%8,%9}, {%0,%1,%2,%3};\n"
        : "+f"(d[0]), "+f"(d[1]), "+f"(d[2]), "+f"(d[3])
        : "r"(a[0]), "r"(a[1]), "r"(a[2]), "r"(a[3]), "r"(b[0]), "r"(b[1]));
}

// ---------------- tensor-core GEMM (3xTF32): C = A * B(^T) ----------------
// Block tile 128x128, K-step 16. 8 warps (2x4), warp tile 64x32.
// TB=0: B is KxN (NN).  TB=1: B is NxK (NT).
// 2-level batch: bz -> (b1 = bz/batch2, b2 = bz%batch2), per-operand strides.
// epi: 0 none, 1 +bias[n], 2 relu(+bias[n])
#define SPAD 20   // shared inner stride (floats): conflict-free fragment access

template <int TB>
__global__ void __launch_bounds__(256)
tgemm(const float* __restrict__ A, const float* __restrict__ B, float* __restrict__ C,
      int M, int N, int K, int lda, int ldb, int ldc,
      long sA1, long sA2, long sB1, long sB2, long sC1, long sC2, int batch2,
      const float* __restrict__ bias, int epi)
{
    __shared__ uint32_t Ah[128 * SPAD], Al[128 * SPAD];
    __shared__ uint32_t Bh[128 * SPAD], Bl[128 * SPAD];

    const int bz = blockIdx.z;
    const int b1 = bz / batch2, b2 = bz % batch2;
    A += (long)b1 * sA1 + (long)b2 * sA2;
    B += (long)b1 * sB1 + (long)b2 * sB2;
    C += (long)b1 * sC1 + (long)b2 * sC2;

    const int m0 = blockIdx.y * 128;
    const int n0 = blockIdx.x * 128;
    const int tid = threadIdx.x;

    const int warp = tid >> 5, lane = tid & 31;
    const int wm = warp >> 2, wn = warp & 3;   // 2 x 4 warp grid
    const int g = lane >> 2, c = lane & 3;

    float acc[4][4][4];
#pragma unroll
    for (int mt = 0; mt < 4; mt++)
#pragma unroll
        for (int nt = 0; nt < 4; nt++)
#pragma unroll
            for (int e = 0; e < 4; e++) acc[mt][nt][e] = 0.f;

    float4 areg[2], breg[2];

    // ---- staging loads (A tile: 128 rows x 16 k; 2 float4 per thread) ----
    auto loadA = [&](int k0) {
#pragma unroll
        for (int j = 0; j < 2; j++) {
            const int f = tid + j * 256;
            const int r = f >> 2, kq = (f & 3) * 4;
            float4 v = {0.f, 0.f, 0.f, 0.f};
            if (m0 + r < M)
                v = *(const float4*)(A + (long)(m0 + r) * lda + k0 + kq);
            areg[j] = v;
        }
    };
    auto loadB = [&](int k0) {
        if (TB == 1) {
#pragma unroll
            for (int j = 0; j < 2; j++) {
                const int f = tid + j * 256;
                const int r = f >> 2, kq = (f & 3) * 4;
                float4 v = {0.f, 0.f, 0.f, 0.f};
                if (n0 + r < N)
                    v = *(const float4*)(B + (long)(n0 + r) * ldb + k0 + kq);
                breg[j] = v;
            }
        } else {
#pragma unroll
            for (int j = 0; j < 2; j++) {
                const int f = tid + j * 256;
                const int kk = f >> 5, n4 = (f & 31) * 4;
                float4 v = {0.f, 0.f, 0.f, 0.f};
                const float* bp = B + (long)(k0 + kk) * ldb + n0 + n4;
                if (n0 + n4 + 3 < N) {
                    v = *(const float4*)bp;
                } else {
                    float t[4] = {0.f, 0.f, 0.f, 0.f};
#pragma unroll
                    for (int i = 0; i < 4; i++) if (n0 + n4 + i < N) t[i] = bp[i];
                    v = {t[0], t[1], t[2], t[3]};
                }
                breg[j] = v;
            }
        }
    };

    auto split4 = [&](float4 v, uint4& h, uint4& l) {
        uint32_t h0 = f2tf32(v.x), h1 = f2tf32(v.y), h2 = f2tf32(v.z), h3 = f2tf32(v.w);
        h = {h0, h1, h2, h3};
        l = {f2tf32(v.x - __uint_as_float(h0)), f2tf32(v.y - __uint_as_float(h1)),
             f2tf32(v.z - __uint_as_float(h2)), f2tf32(v.w - __uint_as_float(h3))};
    };

    auto stTiles = [&]() {
#pragma unroll
        for (int j = 0; j < 2; j++) {
            const int f = tid + j * 256;
            const int r = f >> 2, kq = (f & 3) * 4;
            uint4 h, l;
            split4(areg[j], h, l);
            *(uint4*)&Ah[r * SPAD + kq] = h;
            *(uint4*)&Al[r * SPAD + kq] = l;
        }
        if (TB == 1) {
#pragma unroll
            for (int j = 0; j < 2; j++) {
                const int f = tid + j * 256;
                const int r = f >> 2, kq = (f & 3) * 4;
                uint4 h, l;
                split4(breg[j], h, l);
                *(uint4*)&Bh[r * SPAD + kq] = h;
                *(uint4*)&Bl[r * SPAD + kq] = l;
            }
        } else {
#pragma unroll
            for (int j = 0; j < 2; j++) {
                const int f = tid + j * 256;
                const int kk = f >> 5, n4 = (f & 31) * 4;
                uint4 h, l;
                split4(breg[j], h, l);
                Bh[(n4 + 0) * SPAD + kk] = h.x;  Bl[(n4 + 0) * SPAD + kk] = l.x;
                Bh[(n4 + 1) * SPAD + kk] = h.y;  Bl[(n4 + 1) * SPAD + kk] = l.y;
                Bh[(n4 + 2) * SPAD + kk] = h.z;  Bl[(n4 + 2) * SPAD + kk] = l.z;
                Bh[(n4 + 3) * SPAD + kk] = h.w;  Bl[(n4 + 3) * SPAD + kk] = l.w;
            }
        }
    };

    loadA(0); loadB(0);

    for (int k0 = 0; k0 < K; k0 += 16) {
        stTiles();
        __syncthreads();
        if (k0 + 16 < K) { loadA(k0 + 16); loadB(k0 + 16); }

#pragma unroll
        for (int h = 0; h < 2; h++) {
            const int kb = h * 8;
            uint32_t afh[4][4], afl[4][4], bfh[4][2], bfl[4][2];
#pragma unroll
            for (int mt = 0; mt < 4; mt++) {
                const int rm = wm * 64 + mt * 16 + g;
                const int p0 = rm * SPAD + kb + c;
                const int p1 = (rm + 8) * SPAD + kb + c;
                afh[mt][0] = Ah[p0];     afh[mt][1] = Ah[p1];
                afh[mt][2] = Ah[p0 + 4]; afh[mt][3] = Ah[p1 + 4];
                afl[mt][0] = Al[p0];     afl[mt][1] = Al[p1];
                afl[mt][2] = Al[p0 + 4]; afl[mt][3] = Al[p1 + 4];
            }
#pragma unroll
            for (int nt = 0; nt < 4; nt++) {
                const int rn = wn * 32 + nt * 8 + g;
                const int p = rn * SPAD + kb + c;
                bfh[nt][0] = Bh[p]; bfh[nt][1] = Bh[p + 4];
                bfl[nt][0] = Bl[p]; bfl[nt][1] = Bl[p + 4];
            }
#pragma unroll
            for (int mt = 0; mt < 4; mt++)
#pragma unroll
                for (int nt = 0; nt < 4; nt++) {
                    mma_tf32(acc[mt][nt], afh[mt], bfh[nt]);
                    mma_tf32(acc[mt][nt], afh[mt], bfl[nt]);
                    mma_tf32(acc[mt][nt], afl[mt], bfh[nt]);
                }
        }
        __syncthreads();
    }

    // ---- epilogue ----
#pragma unroll
    for (int mt = 0; mt < 4; mt++) {
        const int row0 = m0 + wm * 64 + mt * 16 + g;
#pragma unroll
        for (int nt = 0; nt < 4; nt++) {
            const int col = n0 + wn * 32 + nt * 8 + c * 2;
            if (col >= N) continue;
            float b0 = 0.f, b1v = 0.f;
            if (epi >= 1) { b0 = bias[col]; b1v = bias[col + 1]; }
#pragma unroll
            for (int half = 0; half < 2; half++) {
                const int row = row0 + half * 8;
                if (row >= M) continue;
                float v0 = acc[mt][nt][half * 2 + 0] + b0;
                float v1 = acc[mt][nt][half * 2 + 1] + b1v;
                if (epi == 2) { v0 = fmaxf(v0, 0.f); v1 = fmaxf(v1, 0.f); }
                float2 o = {v0, v1};
                *(float2*)(C + (long)row * ldc + col) = o;
            }
        }
    }
}

// ---------------- element-wise / reduction kernels ----------------

__global__ void embed_kernel(const int* __restrict__ data, const float* __restrict__ embW,
                             float* __restrict__ core)
{
    long idx = (long)blockIdx.x * 256 + threadIdx.x;
    if (idx >= (long)ROWS * DM) return;
    int r = (int)(idx >> 10), d = (int)(idx & 1023);
    core[idx] = embW[(long)data[r] * DM + d];
}

__global__ void pos_kernel(float* __restrict__ pos)
{
    long idx = (long)blockIdx.x * 256 + threadIdx.x;
    if (idx >= (long)KLEN * DM) return;
    int j = (int)(idx >> 10), d = (int)(idx & 1023);
    float p = (float)(KLEN - 1 - j);
    int t = (d < 512) ? d : d - 512;
    float invf = expf(-((2.0f * (float)t) / (float)DM) * logf(10000.0f));
    float a = p * invf;
    pos[idx] = (d < 512) ? sinf(a) : cosf(a);
}

__global__ void qbias_kernel(const float* __restrict__ q,
                             const float* __restrict__ rwb, const float* __restrict__ rrb,
                             float* __restrict__ qrw, float* __restrict__ qrr)
{
    long idx = (long)blockIdx.x * 256 + threadIdx.x;
    if (idx >= (long)ROWS * DM) return;
    int hd = (int)(idx & 1023);
    float v = q[idx];
    qrw[idx] = v + rwb[hd];
    qrr[idx] = v + rrb[hd];
}

// scores[b,n,i,:] = softmax over j of mask( (AC + shifted BD) * SCALE )
// shifted BD[i,j] = bd_raw[n, i*BSZ+b, j + QLEN-1-i]  (valid for all unmasked j)
__global__ void attn_softmax_kernel(float* __restrict__ sc, const float* __restrict__ bd)
{
    const int i = blockIdx.x, n = blockIdx.y, b = blockIdx.z;
    const int t = threadIdx.x;
    float* row = sc + ((((long)b * NH + n) * QLEN + i) * KLEN);
    const float* bdr = bd + (((long)n * ROWS + (i * BSZ + b)) * KLEN);
    const int limit = i + MEMLEN;       // keep j <= limit
    const int shift = QLEN - 1 - i;

    __shared__ float red[256];
    float v[4];
    float m = -1e30f;
#pragma unroll
    for (int k = 0; k < 4; k++) {
        int j = t + k * 256;
        float x = -1e30f;
        if (j <= limit) x = (row[j] + bdr[j + shift]) * SCALE;
        v[k] = x;
        m = fmaxf(m, x);
    }
    red[t] = m; __syncthreads();
    for (int o = 128; o > 0; o >>= 1) { if (t < o) red[t] = fmaxf(red[t], red[t + o]); __syncthreads(); }
    const float M = red[0];
    __syncthreads();

    float s = 0.f;
#pragma unroll
    for (int k = 0; k < 4; k++) { float e = expf(v[k] - M); v[k] = e; s += e; }
    red[t] = s; __syncthreads();
    for (int o = 128; o > 0; o >>= 1) { if (t < o) red[t] += red[t + o]; __syncthreads(); }
    const float inv = 1.0f / red[0];
#pragma unroll
    for (int k = 0; k < 4; k++) row[t + k * 256] = v[k] * inv;
}

// out = LayerNorm(x + y) * g + b  (row = 1024 elems, one block/row)
__global__ void ln_kernel(const float* __restrict__ x, const float* __restrict__ y,
                          const float* __restrict__ g, const float* __restrict__ b,
                          float* __restrict__ out)
{
    const int r = blockIdx.x, t = threadIdx.x;
    __shared__ float red[256];
    const float* xr = x + (long)r * DM;
    const float* yr = y + (long)r * DM;
    float loc[4];
    float s = 0.f;
#pragma unroll
    for (int k = 0; k < 4; k++) { float v = xr[t + k * 256] + yr[t + k * 256]; loc[k] = v; s += v; }
    red[t] = s; __syncthreads();
    for (int o = 128; o > 0; o >>= 1) { if (t < o) red[t] += red[t + o]; __syncthreads(); }
    const float mu = red[0] * (1.0f / DM);
    __syncthreads();
    float s2 = 0.f;
#pragma unroll
    for (int k = 0; k < 4; k++) { float d = loc[k] - mu; s2 += d * d; }
    red[t] = s2; __syncthreads();
    for (int o = 128; o > 0; o >>= 1) { if (t < o) red[t] += red[t + o]; __syncthreads(); }
    const float rstd = rsqrtf(red[0] * (1.0f / DM) + 1e-5f);
#pragma unroll
    for (int k = 0; k < 4; k++) {
        int d = t + k * 256;
        out[(long)r * DM + d] = (loc[k] - mu) * rstd * g[d] + b[d];
    }
}

// loss[r] = logsumexp(logits[r,:]) - logits[r,target[r]]
__global__ void loss_kernel(const float* __restrict__ logits, const int* __restrict__ target,
                            float* __restrict__ out)
{
    const int r = blockIdx.x, t = threadIdx.x;
    __shared__ float red[256];
    const float* lr = logits + (long)r * NTOK;
    float m = -1e30f;
    for (int j = t; j < NTOK; j += 256) m = fmaxf(m, lr[j]);
    red[t] = m; __syncthreads();
    for (int o = 128; o > 0; o >>= 1) { if (t < o) red[t] = fmaxf(red[t], red[t + o]); __syncthreads(); }
    const float M = red[0];
    __syncthreads();
    float s = 0.f;
    for (int j = t; j < NTOK; j += 256) s += expf(lr[j] - M);
    red[t] = s; __syncthreads();
    for (int o = 128; o > 0; o >>= 1) { if (t < o) red[t] += red[t + o]; __syncthreads(); }
    if (t == 0) out[r] = (logf(red[0]) + M) - lr[target[r]];
}

// ---------------- host orchestration ----------------

static inline dim3 g2(int N, int M, int bz = 1) { return dim3((N + 127) / 128, (M + 127) / 128, bz); }

extern "C" void kernel_launch(void* const* d_in, const int* in_sizes, int n_in,
                              void* d_out, int out_size)
{
    const int*   data   = (const int*)  d_in[0];
    const int*   target = (const int*)  d_in[1];
    const float* memory = (const float*)d_in[2];
    const float* embW   = (const float*)d_in[3];
    const float* rwb    = (const float*)d_in[4];
    const float* rrb    = (const float*)d_in[5];
    const float* Wq     = (const float*)d_in[6];
    const float* Wkv    = (const float*)d_in[7];
    const float* Wr     = (const float*)d_in[8];
    const float* Wo     = (const float*)d_in[9];
    const float* W1     = (const float*)d_in[10];
    const float* b1     = (const float*)d_in[11];
    const float* W2     = (const float*)d_in[12];
    const float* b2     = (const float*)d_in[13];
    const float* ln1g   = (const float*)d_in[14];
    const float* ln1b   = (const float*)d_in[15];
    const float* ln2g   = (const float*)d_in[16];
    const float* ln2b   = (const float*)d_in[17];

    float* out      = (float*)d_out;
    float* out_loss = out;
    float* out_mems = out + ROWS;   // [6, 512, 8, 1024]

    float *core, *xmem, *qb, *qrw, *qrr, *kv, *pos, *rk, *sc, *bd, *vec, *tmp, *ffh, *logit;
    cudaGetSymbolAddress((void**)&core,  g_core);
    cudaGetSymbolAddress((void**)&xmem,  g_xmem);
    cudaGetSymbolAddress((void**)&qb,    g_q);
    cudaGetSymbolAddress((void**)&qrw,   g_qrw);
    cudaGetSymbolAddress((void**)&qrr,   g_qrr);
    cudaGetSymbolAddress((void**)&kv,    g_kv);
    cudaGetSymbolAddress((void**)&pos,   g_pos);
    cudaGetSymbolAddress((void**)&rk,    g_rk);
    cudaGetSymbolAddress((void**)&sc,    g_sc);
    cudaGetSymbolAddress((void**)&bd,    g_bd);
    cudaGetSymbolAddress((void**)&vec,   g_vec);
    cudaGetSymbolAddress((void**)&tmp,   g_tmp);
    cudaGetSymbolAddress((void**)&ffh,   g_ffh);
    cudaGetSymbolAddress((void**)&logit, g_logit);

    const size_t coreBytes = (size_t)ROWS * DM * sizeof(float);

    // embedding + positional encodings
    embed_kernel<<<(ROWS * DM + 255) / 256, 256>>>(data, embW, core);
    pos_kernel  <<<(KLEN * DM + 255) / 256, 256>>>(pos);

    // new_mems[0] = word_emb   (qlen == mem_len, so new_mems[l] == hids[l])
    cudaMemcpyAsync(out_mems, core, coreBytes, cudaMemcpyDeviceToDevice);

    for (int l = 0; l < NL; l++) {
        // x_mem = concat(mem[l], core)
        cudaMemcpyAsync(xmem,             memory + (size_t)l * ROWS * DM, coreBytes, cudaMemcpyDeviceToDevice);
        cudaMemcpyAsync(xmem + ROWS * DM, core,                           coreBytes, cudaMemcpyDeviceToDevice);

        // kv = x_mem @ Wkv[l]   [8192,1024]x[1024,2048]
        tgemm<0><<<g2(2 * HD, KROWS), 256>>>(xmem, Wkv + (size_t)l * DM * 2 * HD, kv,
                                             KROWS, 2 * HD, DM, DM, 2 * HD, 2 * HD,
                                             0, 0, 0, 0, 0, 0, 1, nullptr, 0);
        // q = core @ Wq[l]
        tgemm<0><<<g2(HD, ROWS), 256>>>(core, Wq + (size_t)l * DM * HD, qb,
                                        ROWS, HD, DM, DM, HD, HD,
                                        0, 0, 0, 0, 0, 0, 1, nullptr, 0);
        qbias_kernel<<<(ROWS * DM + 255) / 256, 256>>>(qb, rwb, rrb, qrw, qrr);

        // r_k = pos @ Wr[l]
        tgemm<0><<<g2(HD, KLEN), 256>>>(pos, Wr + (size_t)l * DM * HD, rk,
                                        KLEN, HD, DM, DM, HD, HD,
                                        0, 0, 0, 0, 0, 0, 1, nullptr, 0);

        // AC[b,n,i,j] = (q+rwb)[i,b,n,:] . k[j,b,n,:]   (NT, batched over b*n)
        tgemm<1><<<g2(KLEN, QLEN, BSZ * NH), 256>>>(qrw, kv, sc,
            QLEN, KLEN, DH, BSZ * DM, BSZ * 2 * HD, KLEN,
            (long)DM, (long)DH,
            (long)2 * HD, (long)DH,
            (long)NH * QLEN * KLEN, (long)QLEN * KLEN,
            NH, nullptr, 0);

        // BDraw[n,(i*8+b),j] = (q+rrb)[.,n,:] . r_k[j,n,:]   (NT, batched over n)
        tgemm<1><<<g2(KLEN, ROWS, NH), 256>>>(qrr, rk, bd,
            ROWS, KLEN, DH, DM, DM, KLEN,
            0, (long)DH,
            0, (long)DH,
            0, (long)ROWS * KLEN,
            NH, nullptr, 0);

        // masked softmax with rel-shift applied on the fly
        attn_softmax_kernel<<<dim3(QLEN, NH, BSZ), 256>>>(sc, bd);

        // vec[i,b,n,:] = prob[b,n,i,:] @ v[:,b,n,:]   (NN, batched over b*n)
        tgemm<0><<<g2(DH, QLEN, BSZ * NH), 256>>>(sc, kv + HD, vec,
            QLEN, DH, KLEN, KLEN, BSZ * 2 * HD, BSZ * DM,
            (long)NH * QLEN * KLEN, (long)QLEN * KLEN,
            (long)2 * HD, (long)DH,
            (long)DM, (long)DH,
            NH, nullptr, 0);

        // attn_out = vec @ Wo[l]
        tgemm<0><<<g2(DM, ROWS), 256>>>(vec, Wo + (size_t)l * HD * DM, tmp,
                                        ROWS, DM, HD, HD, DM, DM,
                                        0, 0, 0, 0, 0, 0, 1, nullptr, 0);
        // core = LN(core + attn_out)
        ln_kernel<<<ROWS, 256>>>(core, tmp, ln1g + (size_t)l * DM, ln1b + (size_t)l * DM, core);

        // ffh = relu(core @ W1 + b1)
        tgemm<0><<<g2(DI, ROWS), 256>>>(core, W1 + (size_t)l * DM * DI, ffh,
                                        ROWS, DI, DM, DM, DI, DI,
                                        0, 0, 0, 0, 0, 0, 1, b1 + (size_t)l * DI, 2);
        // ff_out = ffh @ W2 + b2
        tgemm<0><<<g2(DM, ROWS), 256>>>(ffh, W2 + (size_t)l * DI * DM, tmp,
                                        ROWS, DM, DI, DI, DM, DM,
                                        0, 0, 0, 0, 0, 0, 1, b2 + (size_t)l * DM, 1);
        // core = LN(core + ff_out)
        ln_kernel<<<ROWS, 256>>>(core, tmp, ln2g + (size_t)l * DM, ln2b + (size_t)l * DM, core);

        if (l < NL - 1)
            cudaMemcpyAsync(out_mems + (size_t)(l + 1) * ROWS * DM, core, coreBytes,
                            cudaMemcpyDeviceToDevice);
    }

    // logits = core @ emb_W^T   (NT)  [4096,1024]x[32000,1024]^T
    tgemm<1><<<g2(NTOK, ROWS), 256>>>(core, embW, logit,
                                      ROWS, NTOK, DM, DM, DM, NTOK,
                                      0, 0, 0, 0, 0, 0, 1, nullptr, 0);
    // loss
    loss_kernel<<<ROWS, 256>>>(logit, target, out_loss);

    (void)in_sizes; (void)n_in; (void)out_size;
}

// round 3
// speedup vs baseline: 1.7872x; 1.5476x over previous
#include <cuda_runtime.h>
#include <math.h>
#include <stdint.h>

// ---------------- problem constants ----------------
#define QLEN   512
#define MEMLEN 512
#define KLEN   1024
#define BSZ    8
#define NH     16
#define DH     64
#define DM     1024
#define DI     4096
#define NL     6
#define NTOK   32000
#define HD     1024
#define ROWS   (QLEN*BSZ)   // 4096
#define KROWS  (KLEN*BSZ)   // 8192
#define SCALE  0.125f

// ---------------- scratch ----------------
__device__ float g_core [ROWS  * DM];
__device__ float g_xmem [KROWS * DM];
__device__ float g_q    [ROWS  * DM];
__device__ float g_qrw  [ROWS  * DM];
__device__ float g_qrr  [ROWS  * DM];
__device__ float g_kv   [KROWS * 2 * HD];
__device__ float g_pos  [KLEN  * DM];
__device__ float g_rk   [KLEN  * DM];
__device__ float g_sc   [(size_t)BSZ * NH * QLEN * KLEN];
__device__ float g_bd   [(size_t)NH * ROWS * KLEN];
__device__ float g_vec  [ROWS * DM];
__device__ float g_tmp  [ROWS * DM];
__device__ float g_ffh  [ROWS * DI];
__device__ float g_logit[(size_t)ROWS * NTOK];

// ---------------- helpers ----------------
__device__ __forceinline__ uint32_t f2tf32(float x) {
    uint32_t r;
    asm("cvt.rna.tf32.f32 %0, %1;" : "=r"(r) : "f"(x));
    return r;
}

__device__ __forceinline__ void mma_tf32(float* d, const uint32_t* a, const uint32_t* b) {
    asm volatile(
        "mma.sync.aligned.m16n8k8.row.col.f32.tf32.tf32.f32 "
        "{%0,%1,%2,%3}, {%4,%5,%6,%7}, {%8,%9}, {%0,%1,%2,%3};\n"
        : "+f"(d[0]), "+f"(d[1]), "+f"(d[2]), "+f"(d[3])
        : "r"(a[0]), "r"(a[1]), "r"(a[2]), "r"(a[3]), "r"(b[0]), "r"(b[1]));
}

__device__ __forceinline__ void cp16(float* sdst, const float* gsrc, bool pred) {
    uint32_t s = (uint32_t)__cvta_generic_to_shared(sdst);
    int sz = pred ? 16 : 0;
    asm volatile("cp.async.cg.shared.global [%0], [%1], 16, %2;\n"
                 :: "r"(s), "l"(gsrc), "r"(sz));
}
#define CP_COMMIT() asm volatile("cp.async.commit_group;\n")
#define CP_WAIT1()  asm volatile("cp.async.wait_group 1;\n")

// swizzled addresses (float index)
// A / NT-B: [row][32], float4-group q -> q ^ (row&7)
__device__ __forceinline__ int sw_rk(int r, int k) {
    return r * 32 + ((((k >> 2) ^ (r & 7)) & 7) << 2) + (k & 3);
}
// NN-B: [k][128], group q -> q ^ ((k&3)<<1)
__device__ __forceinline__ int sw_kn(int k, int n) {
    return k * 128 + ((((n >> 2) ^ ((k & 3) << 1)) & 31) << 2) + (n & 3);
}

// ---------------- 3xTF32 tensor-core GEMM ----------------
// CTA tile 128x128, K-step 32, 2-stage cp.async double buffer.
// 8 warps (2x4), warp tile 64x32, mma m16n8k8.
// TB=0: B is KxN (NN). TB=1: B is NxK (NT).
// batching as before. epi: 0 none, 1 +bias, 2 relu(+bias).
template <int TB>
__global__ void __launch_bounds__(256)
tgemm(const float* __restrict__ A, const float* __restrict__ B, float* __restrict__ C,
      int M, int N, int K, int lda, int ldb, int ldc,
      long sA1, long sA2, long sB1, long sB2, long sC1, long sC2, int batch2,
      const float* __restrict__ bias, int epi)
{
    extern __shared__ float sm[];
    float* Asm[2] = { sm, sm + 4096 };
    float* Bsm[2] = { sm + 8192, sm + 12288 };

    const int bz = blockIdx.z;
    const int b1 = bz / batch2, b2 = bz % batch2;
    A += (long)b1 * sA1 + (long)b2 * sA2;
    B += (long)b1 * sB1 + (long)b2 * sB2;
    C += (long)b1 * sC1 + (long)b2 * sC2;

    const int m0 = blockIdx.y * 128;
    const int n0 = blockIdx.x * 128;
    const int tid = threadIdx.x;
    const int warp = tid >> 5, lane = tid & 31;
    const int wm = warp >> 2, wn = warp & 3;
    const int g = lane >> 2, c = lane & 3;

    float acc[4][4][4];
#pragma unroll
    for (int mt = 0; mt < 4; mt++)
#pragma unroll
        for (int nt = 0; nt < 4; nt++)
#pragma unroll
            for (int e = 0; e < 4; e++) acc[mt][nt][e] = 0.f;

    const int KT = K >> 5;

    auto issue = [&](int kt, int stage) {
        const int k0 = kt << 5;
        // A: 128 rows x 32k = 1024 float4, 4 per thread
#pragma unroll
        for (int i = 0; i < 4; i++) {
            const int idx = tid + i * 256;
            const int r = idx >> 3, qg = idx & 7;
            cp16(&Asm[stage][r * 32 + (((qg ^ (r & 7)) & 7) << 2)],
                 A + (long)(m0 + r) * lda + k0 + qg * 4, (m0 + r) < M);
        }
        if (TB == 1) {
#pragma unroll
            for (int i = 0; i < 4; i++) {
                const int idx = tid + i * 256;
                const int r = idx >> 3, qg = idx & 7;
                cp16(&Bsm[stage][r * 32 + (((qg ^ (r & 7)) & 7) << 2)],
                     B + (long)(n0 + r) * ldb + k0 + qg * 4, (n0 + r) < N);
            }
        } else {
#pragma unroll
            for (int i = 0; i < 4; i++) {
                const int idx = tid + i * 256;
                const int k = idx >> 5, qg = idx & 31;
                cp16(&Bsm[stage][k * 128 + (((qg ^ ((k & 3) << 1)) & 31) << 2)],
                     B + (long)(k0 + k) * ldb + n0 + qg * 4, (n0 + qg * 4) < N);
            }
        }
    };

    issue(0, 0); CP_COMMIT();
    if (KT > 1) issue(1, 1);
    CP_COMMIT();

    for (int kt = 0; kt < KT; kt++) {
        CP_WAIT1();
        __syncthreads();
        const float* As = Asm[kt & 1];
        const float* Bs = Bsm[kt & 1];

#pragma unroll
        for (int kb8 = 0; kb8 < 4; kb8++) {
            const int kb = kb8 * 8;
            uint32_t afh[4][4], afl[4][4], bfh[4][2], bfl[4][2];
#pragma unroll
            for (int mt = 0; mt < 4; mt++) {
                const int r0 = wm * 64 + mt * 16 + g;
                float x0 = As[sw_rk(r0,     kb + c)];
                float x1 = As[sw_rk(r0 + 8, kb + c)];
                float x2 = As[sw_rk(r0,     kb + c + 4)];
                float x3 = As[sw_rk(r0 + 8, kb + c + 4)];
                uint32_t h0 = f2tf32(x0), h1 = f2tf32(x1), h2 = f2tf32(x2), h3 = f2tf32(x3);
                afh[mt][0] = h0; afh[mt][1] = h1; afh[mt][2] = h2; afh[mt][3] = h3;
                afl[mt][0] = f2tf32(x0 - __uint_as_float(h0));
                afl[mt][1] = f2tf32(x1 - __uint_as_float(h1));
                afl[mt][2] = f2tf32(x2 - __uint_as_float(h2));
                afl[mt][3] = f2tf32(x3 - __uint_as_float(h3));
            }
#pragma unroll
            for (int nt = 0; nt < 4; nt++) {
                const int rn = wn * 32 + nt * 8 + g;
                float y0, y1;
                if (TB == 1) {
                    y0 = Bs[sw_rk(rn, kb + c)];
                    y1 = Bs[sw_rk(rn, kb + c + 4)];
                } else {
                    y0 = Bs[sw_kn(kb + c,     rn)];
                    y1 = Bs[sw_kn(kb + c + 4, rn)];
                }
                uint32_t h0 = f2tf32(y0), h1 = f2tf32(y1);
                bfh[nt][0] = h0; bfh[nt][1] = h1;
                bfl[nt][0] = f2tf32(y0 - __uint_as_float(h0));
                bfl[nt][1] = f2tf32(y1 - __uint_as_float(h1));
            }
#pragma unroll
            for (int mt = 0; mt < 4; mt++)
#pragma unroll
                for (int nt = 0; nt < 4; nt++) {
                    mma_tf32(acc[mt][nt], afh[mt], bfh[nt]);
                    mma_tf32(acc[mt][nt], afh[mt], bfl[nt]);
                    mma_tf32(acc[mt][nt], afl[mt], bfh[nt]);
                }
        }
        __syncthreads();
        if (kt + 2 < KT) issue(kt + 2, kt & 1);
        CP_COMMIT();
    }

    // ---- epilogue ----
#pragma unroll
    for (int mt = 0; mt < 4; mt++) {
        const int row0 = m0 + wm * 64 + mt * 16 + g;
#pragma unroll
        for (int nt = 0; nt < 4; nt++) {
            const int col = n0 + wn * 32 + nt * 8 + c * 2;
            if (col >= N) continue;
            float b0 = 0.f, b1v = 0.f;
            if (epi >= 1) { b0 = bias[col]; b1v = bias[col + 1]; }
#pragma unroll
            for (int half = 0; half < 2; half++) {
                const int row = row0 + half * 8;
                if (row >= M) continue;
                float v0 = acc[mt][nt][half * 2 + 0] + b0;
                float v1 = acc[mt][nt][half * 2 + 1] + b1v;
                if (epi == 2) { v0 = fmaxf(v0, 0.f); v1 = fmaxf(v1, 0.f); }
                float2 o = {v0, v1};
                *(float2*)(C + (long)row * ldc + col) = o;
            }
        }
    }
}

// ---------------- element-wise / reduction kernels ----------------

__global__ void embed_kernel(const int* __restrict__ data, const float* __restrict__ embW,
                             float* __restrict__ core)
{
    long idx = (long)blockIdx.x * 256 + threadIdx.x;
    if (idx >= (long)ROWS * DM) return;
    int r = (int)(idx >> 10), d = (int)(idx & 1023);
    core[idx] = embW[(long)data[r] * DM + d];
}

__global__ void pos_kernel(float* __restrict__ pos)
{
    long idx = (long)blockIdx.x * 256 + threadIdx.x;
    if (idx >= (long)KLEN * DM) return;
    int j = (int)(idx >> 10), d = (int)(idx & 1023);
    float p = (float)(KLEN - 1 - j);
    int t = (d < 512) ? d : d - 512;
    float invf = expf(-((2.0f * (float)t) / (float)DM) * logf(10000.0f));
    float a = p * invf;
    pos[idx] = (d < 512) ? sinf(a) : cosf(a);
}

__global__ void qbias_kernel(const float* __restrict__ q,
                             const float* __restrict__ rwb, const float* __restrict__ rrb,
                             float* __restrict__ qrw, float* __restrict__ qrr)
{
    long idx = (long)blockIdx.x * 256 + threadIdx.x;
    if (idx >= (long)ROWS * DM) return;
    int hd = (int)(idx & 1023);
    float v = q[idx];
    qrw[idx] = v + rwb[hd];
    qrr[idx] = v + rrb[hd];
}

__global__ void attn_softmax_kernel(float* __restrict__ sc, const float* __restrict__ bd)
{
    const int i = blockIdx.x, n = blockIdx.y, b = blockIdx.z;
    const int t = threadIdx.x;
    float* row = sc + ((((long)b * NH + n) * QLEN + i) * KLEN);
    const float* bdr = bd + (((long)n * ROWS + (i * BSZ + b)) * KLEN);
    const int limit = i + MEMLEN;
    const int shift = QLEN - 1 - i;

    __shared__ float red[256];
    float v[4];
    float m = -1e30f;
#pragma unroll
    for (int k = 0; k < 4; k++) {
        int j = t + k * 256;
        float x = -1e30f;
        if (j <= limit) x = (row[j] + bdr[j + shift]) * SCALE;
        v[k] = x;
        m = fmaxf(m, x);
    }
    red[t] = m; __syncthreads();
    for (int o = 128; o > 0; o >>= 1) { if (t < o) red[t] = fmaxf(red[t], red[t + o]); __syncthreads(); }
    const float M = red[0];
    __syncthreads();

    float s = 0.f;
#pragma unroll
    for (int k = 0; k < 4; k++) { float e = expf(v[k] - M); v[k] = e; s += e; }
    red[t] = s; __syncthreads();
    for (int o = 128; o > 0; o >>= 1) { if (t < o) red[t] += red[t + o]; __syncthreads(); }
    const float inv = 1.0f / red[0];
#pragma unroll
    for (int k = 0; k < 4; k++) row[t + k * 256] = v[k] * inv;
}

__global__ void ln_kernel(const float* __restrict__ x, const float* __restrict__ y,
                          const float* __restrict__ g, const float* __restrict__ b,
                          float* __restrict__ out)
{
    const int r = blockIdx.x, t = threadIdx.x;
    __shared__ float red[256];
    const float* xr = x + (long)r * DM;
    const float* yr = y + (long)r * DM;
    float loc[4];
    float s = 0.f;
#pragma unroll
    for (int k = 0; k < 4; k++) { float v = xr[t + k * 256] + yr[t + k * 256]; loc[k] = v; s += v; }
    red[t] = s; __syncthreads();
    for (int o = 128; o > 0; o >>= 1) { if (t < o) red[t] += red[t + o]; __syncthreads(); }
    const float mu = red[0] * (1.0f / DM);
    __syncthreads();
    float s2 = 0.f;
#pragma unroll
    for (int k = 0; k < 4; k++) { float d = loc[k] - mu; s2 += d * d; }
    red[t] = s2; __syncthreads();
    for (int o = 128; o > 0; o >>= 1) { if (t < o) red[t] += red[t + o]; __syncthreads(); }
    const float rstd = rsqrtf(red[0] * (1.0f / DM) + 1e-5f);
#pragma unroll
    for (int k = 0; k < 4; k++) {
        int d = t + k * 256;
        out[(long)r * DM + d] = (loc[k] - mu) * rstd * g[d] + b[d];
    }
}

__global__ void loss_kernel(const float* __restrict__ logits, const int* __restrict__ target,
                            float* __restrict__ out)
{
    const int r = blockIdx.x, t = threadIdx.x;
    __shared__ float red[256];
    const float* lr = logits + (long)r * NTOK;
    float m = -1e30f;
    for (int j = t; j < NTOK; j += 256) m = fmaxf(m, lr[j]);
    red[t] = m; __syncthreads();
    for (int o = 128; o > 0; o >>= 1) { if (t < o) red[t] = fmaxf(red[t], red[t + o]); __syncthreads(); }
    const float M = red[0];
    __syncthreads();
    float s = 0.f;
    for (int j = t; j < NTOK; j += 256) s += expf(lr[j] - M);
    red[t] = s; __syncthreads();
    for (int o = 128; o > 0; o >>= 1) { if (t < o) red[t] += red[t + o]; __syncthreads(); }
    if (t == 0) out[r] = (logf(red[0]) + M) - lr[target[r]];
}

// ---------------- host orchestration ----------------

static inline dim3 g2(int N, int M, int bz = 1) { return dim3((N + 127) / 128, (M + 127) / 128, bz); }
#define SMEM_GEMM (64 * 1024)

extern "C" void kernel_launch(void* const* d_in, const int* in_sizes, int n_in,
                              void* d_out, int out_size)
{
    const int*   data   = (const int*)  d_in[0];
    const int*   target = (const int*)  d_in[1];
    const float* memory = (const float*)d_in[2];
    const float* embW   = (const float*)d_in[3];
    const float* rwb    = (const float*)d_in[4];
    const float* rrb    = (const float*)d_in[5];
    const float* Wq     = (const float*)d_in[6];
    const float* Wkv    = (const float*)d_in[7];
    const float* Wr     = (const float*)d_in[8];
    const float* Wo     = (const float*)d_in[9];
    const float* W1     = (const float*)d_in[10];
    const float* b1     = (const float*)d_in[11];
    const float* W2     = (const float*)d_in[12];
    const float* b2     = (const float*)d_in[13];
    const float* ln1g   = (const float*)d_in[14];
    const float* ln1b   = (const float*)d_in[15];
    const float* ln2g   = (const float*)d_in[16];
    const float* ln2b   = (const float*)d_in[17];

    float* out      = (float*)d_out;
    float* out_loss = out;
    float* out_mems = out + ROWS;

    float *core, *xmem, *qb, *qrw, *qrr, *kv, *pos, *rk, *sc, *bd, *vec, *tmp, *ffh, *logit;
    cudaGetSymbolAddress((void**)&core,  g_core);
    cudaGetSymbolAddress((void**)&xmem,  g_xmem);
    cudaGetSymbolAddress((void**)&qb,    g_q);
    cudaGetSymbolAddress((void**)&qrw,   g_qrw);
    cudaGetSymbolAddress((void**)&qrr,   g_qrr);
    cudaGetSymbolAddress((void**)&kv,    g_kv);
    cudaGetSymbolAddress((void**)&pos,   g_pos);
    cudaGetSymbolAddress((void**)&rk,    g_rk);
    cudaGetSymbolAddress((void**)&sc,    g_sc);
    cudaGetSymbolAddress((void**)&bd,    g_bd);
    cudaGetSymbolAddress((void**)&vec,   g_vec);
    cudaGetSymbolAddress((void**)&tmp,   g_tmp);
    cudaGetSymbolAddress((void**)&ffh,   g_ffh);
    cudaGetSymbolAddress((void**)&logit, g_logit);

    static int smem_set = 0;
    if (!smem_set) {
        cudaFuncSetAttribute(tgemm<0>, cudaFuncAttributeMaxDynamicSharedMemorySize, SMEM_GEMM);
        cudaFuncSetAttribute(tgemm<1>, cudaFuncAttributeMaxDynamicSharedMemorySize, SMEM_GEMM);
        smem_set = 1;
    }

    const size_t coreBytes = (size_t)ROWS * DM * sizeof(float);

    embed_kernel<<<(ROWS * DM + 255) / 256, 256>>>(data, embW, core);
    pos_kernel  <<<(KLEN * DM + 255) / 256, 256>>>(pos);

    cudaMemcpyAsync(out_mems, core, coreBytes, cudaMemcpyDeviceToDevice);

    for (int l = 0; l < NL; l++) {
        cudaMemcpyAsync(xmem,             memory + (size_t)l * ROWS * DM, coreBytes, cudaMemcpyDeviceToDevice);
        cudaMemcpyAsync(xmem + ROWS * DM, core,                           coreBytes, cudaMemcpyDeviceToDevice);

        tgemm<0><<<g2(2 * HD, KROWS), 256, SMEM_GEMM>>>(xmem, Wkv + (size_t)l * DM * 2 * HD, kv,
                                             KROWS, 2 * HD, DM, DM, 2 * HD, 2 * HD,
                                             0, 0, 0, 0, 0, 0, 1, nullptr, 0);
        tgemm<0><<<g2(HD, ROWS), 256, SMEM_GEMM>>>(core, Wq + (size_t)l * DM * HD, qb,
                                        ROWS, HD, DM, DM, HD, HD,
                                        0, 0, 0, 0, 0, 0, 1, nullptr, 0);
        qbias_kernel<<<(ROWS * DM + 255) / 256, 256>>>(qb, rwb, rrb, qrw, qrr);

        tgemm<0><<<g2(HD, KLEN), 256, SMEM_GEMM>>>(pos, Wr + (size_t)l * DM * HD, rk,
                                        KLEN, HD, DM, DM, HD, HD,
                                        0, 0, 0, 0, 0, 0, 1, nullptr, 0);

        tgemm<1><<<g2(KLEN, QLEN, BSZ * NH), 256, SMEM_GEMM>>>(qrw, kv, sc,
            QLEN, KLEN, DH, BSZ * DM, BSZ * 2 * HD, KLEN,
            (long)DM, (long)DH,
            (long)2 * HD, (long)DH,
            (long)NH * QLEN * KLEN, (long)QLEN * KLEN,
            NH, nullptr, 0);

        tgemm<1><<<g2(KLEN, ROWS, NH), 256, SMEM_GEMM>>>(qrr, rk, bd,
            ROWS, KLEN, DH, DM, DM, KLEN,
            0, (long)DH,
            0, (long)DH,
            0, (long)ROWS * KLEN,
            NH, nullptr, 0);

        attn_softmax_kernel<<<dim3(QLEN, NH, BSZ), 256>>>(sc, bd);

        tgemm<0><<<g2(DH, QLEN, BSZ * NH), 256, SMEM_GEMM>>>(sc, kv + HD, vec,
            QLEN, DH, KLEN, KLEN, BSZ * 2 * HD, BSZ * DM,
            (long)NH * QLEN * KLEN, (long)QLEN * KLEN,
            (long)2 * HD, (long)DH,
            (long)DM, (long)DH,
            NH, nullptr, 0);

        tgemm<0><<<g2(DM, ROWS), 256, SMEM_GEMM>>>(vec, Wo + (size_t)l * HD * DM, tmp,
                                        ROWS, DM, HD, HD, DM, DM,
                                        0, 0, 0, 0, 0, 0, 1, nullptr, 0);
        ln_kernel<<<ROWS, 256>>>(core, tmp, ln1g + (size_t)l * DM, ln1b + (size_t)l * DM, core);

        tgemm<0><<<g2(DI, ROWS), 256, SMEM_GEMM>>>(core, W1 + (size_t)l * DM * DI, ffh,
                                        ROWS, DI, DM, DM, DI, DI,
                                        0, 0, 0, 0, 0, 0, 1, b1 + (size_t)l * DI, 2);
        tgemm<0><<<g2(DM, ROWS), 256, SMEM_GEMM>>>(ffh, W2 + (size_t)l * DI * DM, tmp,
                                        ROWS, DM, DI, DI, DM, DM,
                                        0, 0, 0, 0, 0, 0, 1, b2 + (size_t)l * DM, 1);
        ln_kernel<<<ROWS, 256>>>(core, tmp, ln2g + (size_t)l * DM, ln2b + (size_t)l * DM, core);

        if (l < NL - 1)
            cudaMemcpyAsync(out_mems + (size_t)(l + 1) * ROWS * DM, core, coreBytes,
                            cudaMemcpyDeviceToDevice);
    }

    tgemm<1><<<g2(NTOK, ROWS), 256, SMEM_GEMM>>>(core, embW, logit,
                                      ROWS, NTOK, DM, DM, DM, NTOK,
                                      0, 0, 0, 0, 0, 0, 1, nullptr, 0);
    loss_kernel<<<ROWS, 256>>>(logit, target, out_loss);

    (void)in_sizes; (void)n_in; (void)out_size;
}